// round 13
// baseline (speedup 1.0000x reference)
#include <cuda_runtime.h>
#include <cuda_bf16.h>
#include <stdint.h>

#define N_TOKENS_TOTAL 16384
#define D_PROJ 1024
#define EMB_SCALE 32.0f
#define MAX_TILES 280
#define NTHREADS 256
#define NS 3
#define PART_ENTRIES 132          // max c0 split entries (tiles0*ks0)

// ---------------- scratch ----------------
__device__ int g_cnt[4];
__device__ int g_tok[4][N_TOKENS_TOTAL];
__device__ int g_loc[4][N_TOKENS_TOTAL];
__device__ int g_tile_c[MAX_TILES];
__device__ int g_tile_m0[MAX_TILES];
__device__ int g_tile_ke[MAX_TILES];    // effective K for this entry
__device__ int g_tile_kb[MAX_TILES];    // k16 base (global) for this entry
__device__ int g_tile_slot[MAX_TILES];  // partial slot or -1
__device__ int g_total_tiles;
__device__ int g_ks0;

// tf32 fragment-ordered scratch
#define A_ELEMS (16384u * 1360u)
#define B_ELEMS (1024u * 1360u)
__device__ __align__(16) float g_a[A_ELEMS];
__device__ __align__(16) float g_b[B_ELEMS];
// c0 split partials: [entry][128 rows][1024 cols]
__device__ __align__(16) float g_part[(size_t)PART_ENTRIES * 131072];

__constant__ int c_K[4]    = {1024, 256, 64, 16};
__constant__ int c_logK[4] = {10, 8, 6, 4};
__constant__ unsigned c_AOFF[4] = {0u, 16384u*1024u, 16384u*1280u, 16384u*1344u};
__constant__ unsigned c_BOFF[4] = {0u, 1024u*1024u, 1024u*1280u, 1024u*1344u};

// ---------------- helpers ----------------
__device__ __forceinline__ uint32_t smem_u32(const void* p) {
    uint32_t a;
    asm("{ .reg .u64 t; cvta.to.shared.u64 t, %1; cvt.u32.u64 %0, t; }" : "=r"(a) : "l"(p));
    return a;
}
__device__ __forceinline__ uint32_t f2tf(float x) {
    uint32_t r;
    asm("cvt.rna.tf32.f32 %0, %1;" : "=r"(r) : "f"(x));
    return r;
}
__device__ __forceinline__ void mma_tf32(float* c, const uint32_t* a,
                                         uint32_t b0, uint32_t b1) {
    asm volatile(
        "mma.sync.aligned.m16n8k8.row.col.f32.tf32.tf32.f32 "
        "{%0,%1,%2,%3}, {%4,%5,%6,%7}, {%8,%9}, {%0,%1,%2,%3};"
        : "+f"(c[0]), "+f"(c[1]), "+f"(c[2]), "+f"(c[3])
        : "r"(a[0]), "r"(a[1]), "r"(a[2]), "r"(a[3]), "r"(b0), "r"(b1));
}
__device__ __forceinline__ void lds128(uint32_t* r, uint32_t addr) {
    asm volatile("ld.shared.v4.b32 {%0,%1,%2,%3}, [%4];"
                 : "=r"(r[0]), "=r"(r[1]), "=r"(r[2]), "=r"(r[3]) : "r"(addr));
}
__device__ __forceinline__ void cp16(uint32_t dst, const void* src) {
    asm volatile("cp.async.cg.shared.global [%0], [%1], 16;"
                 :: "r"(dst), "l"(src) : "memory");
}
#define CP_COMMIT() asm volatile("cp.async.commit_group;" ::: "memory")
#define CP_WAIT1()  asm volatile("cp.async.wait_group 1;" ::: "memory")

// ---------------- kernel 1: zero ----------------
__global__ void zero_kernel() {
    if (threadIdx.x < 4) g_cnt[threadIdx.x] = 0;
}

// ---------------- kernel 2: bucket ----------------
__global__ void bucket_kernel(const int* __restrict__ inp, int n) {
    __shared__ int s_cnt[4];
    __shared__ int s_base[4];
    const int t = blockIdx.x * blockDim.x + threadIdx.x;
    if (threadIdx.x < 4) s_cnt[threadIdx.x] = 0;
    __syncthreads();
    int v = 0, c = 0, l = 0, rank = 0;
    const bool valid = t < n;
    if (valid) {
        v = inp[t];
        if (v < 20000)       { c = 0; l = 0; }
        else if (v < 40000)  { c = 1; l = 20000; }
        else if (v < 200000) { c = 2; l = 40000; }
        else                 { c = 3; l = 200000; }
        rank = atomicAdd(&s_cnt[c], 1);
    }
    __syncthreads();
    if (threadIdx.x < 4)
        s_base[threadIdx.x] = atomicAdd(&g_cnt[threadIdx.x], s_cnt[threadIdx.x]);
    __syncthreads();
    if (valid) {
        const int p = s_base[c] + rank;
        g_tok[c][p] = t;
        g_loc[c][p] = v - l;
    }
}

// ---------------- kernel 3: conversion + split-K plan ----------------
__global__ void conv_kernel(
    const float* __restrict__ e0, const float* __restrict__ e1,
    const float* __restrict__ e2, const float* __restrict__ e3,
    const float* __restrict__ p0, const float* __restrict__ p1,
    const float* __restrict__ p2, const float* __restrict__ p3)
{
    if (blockIdx.y == 0 && blockIdx.x == 0) {
        __shared__ int offs[5];
        __shared__ int sh_lks0;
        if (threadIdx.x == 0) {
            const int t0 = (g_cnt[0] + 127) >> 7;
            const int ks0 = (t0 <= 33) ? 4 : (t0 <= 66 ? 2 : 1);
            const int lks0 = (ks0 == 4) ? 2 : (ks0 == 2 ? 1 : 0);
            g_ks0 = ks0;
            sh_lks0 = lks0;
            offs[0] = 0;
            offs[1] = t0 << lks0;
            for (int c = 1; c < 4; c++)
                offs[c + 1] = offs[c] + ((g_cnt[c] + 127) >> 7);
            g_total_tiles = offs[4];
        }
        __syncthreads();
        const int total = offs[4];
        const int lks0 = sh_lks0;
        for (int i = threadIdx.x; i < total; i += blockDim.x) {
            if (i < offs[1]) {                       // c0 split entries
                const int mtile = i >> lks0;
                const int s = i & ((1 << lks0) - 1);
                const int ke = 1024 >> lks0;
                g_tile_c[i] = 0;
                g_tile_m0[i] = mtile << 7;
                g_tile_ke[i] = ke;
                g_tile_kb[i] = s * (ke >> 4);
                g_tile_slot[i] = i;
            } else {
                int c = 1;
                while (i >= offs[c + 1]) c++;
                g_tile_c[i] = c;
                g_tile_m0[i] = (i - offs[c]) << 7;
                g_tile_ke[i] = c_K[c];
                g_tile_kb[i] = 0;
                g_tile_slot[i] = -1;
            }
        }
    }

    const int y = blockIdx.y;
    const unsigned stride = gridDim.x * blockDim.x;
    const unsigned t0 = blockIdx.x * blockDim.x + threadIdx.x;

    if (y < 4) {
        const int c = y;
        const float* proj = c == 0 ? p0 : c == 1 ? p1 : c == 2 ? p2 : p3;
        const int K = c_K[c];
        const int lkk = c_logK[c] - 4;
        const unsigned base = c_BOFF[c];
        const unsigned nu = (unsigned)(K >> 4) << 12;
        for (unsigned u = t0; u < nu; u += stride) {
            const int lane = u & 31;
            const int k16  = (u >> 5) & ((1u << lkk) - 1);
            const int nt   = u >> (5 + lkk);
            const int n    = nt * 8 + (lane >> 2);
            const int cb   = k16 * 16 + (lane & 3);
            const float* p = proj + (size_t)n * K + cb;
            uint4 v = make_uint4(f2tf(p[0]), f2tf(p[4]), f2tf(p[8]), f2tf(p[12]));
            *reinterpret_cast<uint4*>(g_b + base + ((size_t)u << 2)) = v;
        }
    } else {
        const int c = y - 4;
        const float* emb = c == 0 ? e0 : c == 1 ? e1 : c == 2 ? e2 : e3;
        const int K = c_K[c];
        const int lkk = c_logK[c] - 4;
        const int cnt = g_cnt[c];
        const unsigned base = c_AOFF[c];
        const int mtiles = (cnt + 127) >> 7;
        const unsigned nu = (unsigned)mtiles * ((unsigned)(K >> 4) << 9);
        for (unsigned u = t0; u < nu; u += stride) {
            const int lane  = u & 31;
            const int k8r   = (u >> 5) & 1;
            const int st    = (u >> 6) & 7;
            const int k16   = (u >> 9) & ((1u << lkk) - 1);
            const int mtile = u >> (9 + lkk);
            const int r0 = mtile * 128 + st * 16 + (lane >> 2);
            const int r1 = r0 + 8;
            const int cb = k16 * 16 + k8r * 8 + (lane & 3);
            float x0 = 0.f, x1 = 0.f, x2 = 0.f, x3 = 0.f;
            if (r0 < cnt) {
                const float* p = emb + (size_t)g_loc[c][r0] * K + cb;
                x0 = p[0]; x2 = p[4];
            }
            if (r1 < cnt) {
                const float* p = emb + (size_t)g_loc[c][r1] * K + cb;
                x1 = p[0]; x3 = p[4];
            }
            uint4 v = make_uint4(f2tf(x0), f2tf(x1), f2tf(x2), f2tf(x3));
            *reinterpret_cast<uint4*>(g_a + base + ((size_t)u << 2)) = v;
        }
    }
}

// ---------------- kernel 4: tf32 GEMM (split-K c0 via partials) ----------------
#define STG_A 0
#define STG_B 16384
#define STG_STRIDE 24576
#define SMEM_BYTES (NS * STG_STRIDE)

__global__ __launch_bounds__(NTHREADS, 3) void gemm_mma_kernel(float* __restrict__ out) {
    extern __shared__ char smem[];
    const uint32_t sb = smem_u32(smem);

    const int tile = blockIdx.y;
    if (tile >= g_total_tiles) return;

    const int cluster = g_tile_c[tile];
    const int m0 = g_tile_m0[tile];
    const int ke = g_tile_ke[tile];
    const int kb = g_tile_kb[tile];
    const int slot = g_tile_slot[tile];
    const int cnt = g_cnt[cluster];
    const int K = c_K[cluster];
    const int lkk = c_logK[cluster] - 4;
    const int n0 = blockIdx.x * 64;

    const float* abase = g_a + c_AOFF[cluster] + (size_t)m0 * K;
    const float* bbase = g_b + c_BOFF[cluster];
    const int ntg0 = n0 >> 3;

    const int tid  = threadIdx.x;
    const int lane = tid & 31;
    const int wid  = tid >> 5;

    const int nchunks = (ke + 31) >> 5;

    auto issue = [&](int ic) {
        const int k16l = ic << 1;
        const int nk16 = ((ke >> 4) - k16l) >= 2 ? 2 : 1;
        const int k16g = kb + k16l;
        const uint32_t bo = sb + (uint32_t)(ic % NS) * STG_STRIDE;
        // A: contiguous nk16*8KB
        const float* asrc = abase + ((size_t)k16g << 11);
        const int agr = nk16 << 9;
        for (int ci = tid; ci < agr; ci += NTHREADS)
            cp16(bo + STG_A + ci * 16, asrc + ci * 4);
        // B: 8 ntiles, each contiguous nk16*512B
        const int lgb = 5 + (nk16 >> 1);
        const int bgr = nk16 << 8;
        for (int ci = tid; ci < bgr; ci += NTHREADS) {
            const int nt = ci >> lgb;
            const int rem = ci & ((1 << lgb) - 1);
            const float* bsrc =
                bbase + ((((size_t)(ntg0 + nt) << lkk) + k16g) << 7) + rem * 4;
            cp16(bo + STG_B + (nt << (lgb + 4)) + (rem << 4), bsrc);
        }
    };

    for (int s = 0; s < NS - 1; s++) {
        if (s < nchunks) issue(s);
        CP_COMMIT();
    }

    float acc[2][4][4] = {};

    auto kstep = [&](uint32_t bo, int k16r, int bstr) {
        uint32_t aA[2][4], aB[2][4];
#pragma unroll
        for (int mt = 0; mt < 2; mt++) {
            const int st = (wid & 3) * 2 + mt;
            const uint32_t ad = bo + STG_A + k16r * 8192 + st * 1024 + lane * 16;
            lds128(aA[mt], ad);
            lds128(aB[mt], ad + 512);
        }
#pragma unroll
        for (int nt = 0; nt < 4; nt++) {
            const int ntb = (wid >> 2) * 4 + nt;
            uint32_t b[4];
            lds128(b, bo + STG_B + ntb * bstr + k16r * 512 + lane * 16);
#pragma unroll
            for (int mt = 0; mt < 2; mt++) {
                mma_tf32(acc[mt][nt], aA[mt], b[0], b[1]);
                mma_tf32(acc[mt][nt], aB[mt], b[2], b[3]);
            }
        }
    };

    for (int ic = 0; ic < nchunks; ic++) {
        CP_WAIT1();
        __syncthreads();
        if (ic + NS - 1 < nchunks) issue(ic + NS - 1);
        CP_COMMIT();

        const int nk16 = ((ke >> 4) - (ic << 1)) >= 2 ? 2 : 1;
        const int bstr = nk16 << 9;
        const uint32_t bo = sb + (uint32_t)(ic % NS) * STG_STRIDE;
        kstep(bo, 0, bstr);
        if (nk16 == 2) kstep(bo, 1, bstr);
    }

    if (slot >= 0) {
        // partial path: unscaled, linear layout, unconditional coalesced stores
        float* pp = g_part + (size_t)slot * 131072 + n0 + (wid >> 2) * 32 + (lane & 3) * 2;
#pragma unroll
        for (int mt = 0; mt < 2; mt++) {
            const int r0l = (wid & 3) * 32 + mt * 16 + (lane >> 2);
#pragma unroll
            for (int nt = 0; nt < 4; nt++) {
                *reinterpret_cast<float2*>(pp + (size_t)r0l * 1024 + nt * 8) =
                    make_float2(acc[mt][nt][0], acc[mt][nt][1]);
                *reinterpret_cast<float2*>(pp + (size_t)(r0l + 8) * 1024 + nt * 8) =
                    make_float2(acc[mt][nt][2], acc[mt][nt][3]);
            }
        }
    } else {
        // direct path: scale + scatter
#pragma unroll
        for (int mt = 0; mt < 2; mt++) {
            const int r0 = m0 + (wid & 3) * 32 + mt * 16 + (lane >> 2);
            const int r1 = r0 + 8;
            const int ncol = n0 + (wid >> 2) * 32 + (lane & 3) * 2;
            float* q0 = nullptr;
            float* q1 = nullptr;
            if (r0 < cnt) q0 = out + (size_t)g_tok[cluster][r0] * D_PROJ + ncol;
            if (r1 < cnt) q1 = out + (size_t)g_tok[cluster][r1] * D_PROJ + ncol;
#pragma unroll
            for (int nt = 0; nt < 4; nt++) {
                if (q0) *reinterpret_cast<float2*>(q0 + nt * 8) =
                    make_float2(acc[mt][nt][0] * EMB_SCALE, acc[mt][nt][1] * EMB_SCALE);
                if (q1) *reinterpret_cast<float2*>(q1 + nt * 8) =
                    make_float2(acc[mt][nt][2] * EMB_SCALE, acc[mt][nt][3] * EMB_SCALE);
            }
        }
    }
}

// ---------------- kernel 5: c0 split reduction + scale + scatter ----------------
__global__ void reduce_kernel(float* __restrict__ out) {
    const int cnt0 = g_cnt[0];
    if (cnt0 == 0) return;
    const int ks0 = g_ks0;
    const int lks0 = (ks0 == 4) ? 2 : (ks0 == 2 ? 1 : 0);
    const unsigned total = (unsigned)cnt0 << 8;     // float4 units per row = 256
    const unsigned stride = gridDim.x * blockDim.x;
    for (unsigned u = blockIdx.x * blockDim.x + threadIdx.x; u < total; u += stride) {
        const int r = (int)(u >> 8);
        const int c4 = (int)(u & 255u);
        const int mtile = r >> 7;
        const int rl = r & 127;
        const float* p = g_part + ((size_t)(mtile << lks0) * 131072) +
                         (size_t)rl * 1024 + c4 * 4;
        float4 s = *reinterpret_cast<const float4*>(p);
        for (int i = 1; i < ks0; i++) {
            const float4 t = *reinterpret_cast<const float4*>(p + (size_t)i * 131072);
            s.x += t.x; s.y += t.y; s.z += t.z; s.w += t.w;
        }
        s.x *= EMB_SCALE; s.y *= EMB_SCALE; s.z *= EMB_SCALE; s.w *= EMB_SCALE;
        *reinterpret_cast<float4*>(out + (size_t)g_tok[0][r] * D_PROJ + c4 * 4) = s;
    }
}

// ---------------- launch ----------------
extern "C" void kernel_launch(void* const* d_in, const int* in_sizes, int n_in,
                              void* d_out, int out_size) {
    const int* inp = (const int*)d_in[0];
    const float* emb[4];
    const float* proj[4];

    if (n_in >= 9 && in_sizes[2] == 1024 * 1024) {
        for (int i = 0; i < 4; i++) {
            emb[i]  = (const float*)d_in[1 + 2 * i];
            proj[i] = (const float*)d_in[2 + 2 * i];
        }
    } else {
        for (int i = 0; i < 4; i++) {
            emb[i]  = (const float*)d_in[1 + i];
            proj[i] = (const float*)d_in[5 + i];
        }
    }

    float* out = (float*)d_out;
    const int n_tok = in_sizes[0];

    cudaFuncSetAttribute(gemm_mma_kernel,
                         cudaFuncAttributeMaxDynamicSharedMemorySize, SMEM_BYTES);

    zero_kernel<<<1, 32>>>();
    bucket_kernel<<<(n_tok + 255) / 256, 256>>>(inp, n_tok);
    conv_kernel<<<dim3(148, 8), 256>>>(emb[0], emb[1], emb[2], emb[3],
                                       proj[0], proj[1], proj[2], proj[3]);

    dim3 grid(D_PROJ / 64, MAX_TILES);
    gemm_mma_kernel<<<grid, NTHREADS, SMEM_BYTES>>>(out);
    reduce_kernel<<<256, 256>>>(out);
}

// round 14
// speedup vs baseline: 1.2575x; 1.2575x over previous
#include <cuda_runtime.h>
#include <cuda_bf16.h>
#include <stdint.h>

#define N_TOKENS_TOTAL 16384
#define D_PROJ 1024
#define EMB_SCALE 32.0f
#define MAX_TILES 136
#define NTHREADS 256
#define NS 3

// ---------------- scratch ----------------
__device__ int g_cnt[4];
__device__ int g_tok[4][N_TOKENS_TOTAL];
__device__ int g_loc[4][N_TOKENS_TOTAL];
__device__ int g_tile_c[MAX_TILES];
__device__ int g_tile_m0[MAX_TILES];
__device__ int g_total_tiles;

// tf32 fragment-ordered scratch (f32 containers holding tf32 bits)
#define A_ELEMS (16384u * 1360u)
#define B_ELEMS (1024u * 1360u)
__device__ __align__(16) float g_a[A_ELEMS];
__device__ __align__(16) float g_b[B_ELEMS];

__constant__ int c_K[4]    = {1024, 256, 64, 16};
__constant__ int c_logK[4] = {10, 8, 6, 4};          // log2 K
__constant__ unsigned c_AOFF[4] = {0u, 16384u*1024u, 16384u*1280u, 16384u*1344u};
__constant__ unsigned c_BOFF[4] = {0u, 1024u*1024u, 1024u*1280u, 1024u*1344u};

// ---------------- helpers ----------------
__device__ __forceinline__ uint32_t smem_u32(const void* p) {
    uint32_t a;
    asm("{ .reg .u64 t; cvta.to.shared.u64 t, %1; cvt.u32.u64 %0, t; }" : "=r"(a) : "l"(p));
    return a;
}
__device__ __forceinline__ uint32_t f2tf(float x) {
    uint32_t r;
    asm("cvt.rna.tf32.f32 %0, %1;" : "=r"(r) : "f"(x));
    return r;
}
__device__ __forceinline__ void mma_tf32(float* c, const uint32_t* a,
                                         uint32_t b0, uint32_t b1) {
    asm volatile(
        "mma.sync.aligned.m16n8k8.row.col.f32.tf32.tf32.f32 "
        "{%0,%1,%2,%3}, {%4,%5,%6,%7}, {%8,%9}, {%0,%1,%2,%3};"
        : "+f"(c[0]), "+f"(c[1]), "+f"(c[2]), "+f"(c[3])
        : "r"(a[0]), "r"(a[1]), "r"(a[2]), "r"(a[3]), "r"(b0), "r"(b1));
}
__device__ __forceinline__ void lds128(uint32_t* r, uint32_t addr) {
    asm volatile("ld.shared.v4.b32 {%0,%1,%2,%3}, [%4];"
                 : "=r"(r[0]), "=r"(r[1]), "=r"(r[2]), "=r"(r[3]) : "r"(addr));
}
__device__ __forceinline__ void cp16(uint32_t dst, const void* src) {
    asm volatile("cp.async.cg.shared.global [%0], [%1], 16;"
                 :: "r"(dst), "l"(src) : "memory");
}
#define CP_COMMIT() asm volatile("cp.async.commit_group;" ::: "memory")
#define CP_WAIT1()  asm volatile("cp.async.wait_group 1;" ::: "memory")

// ---------------- kernel: bucket (block-aggregated atomics) ----------------
__global__ void bucket_kernel(const int* __restrict__ inp, int n) {
    __shared__ int s_cnt[4];
    __shared__ int s_base[4];
    const int t = blockIdx.x * blockDim.x + threadIdx.x;
    if (threadIdx.x < 4) s_cnt[threadIdx.x] = 0;
    __syncthreads();
    int v = 0, c = 0, l = 0, rank = 0;
    const bool valid = t < n;
    if (valid) {
        v = inp[t];
        if (v < 20000)       { c = 0; l = 0; }
        else if (v < 40000)  { c = 1; l = 20000; }
        else if (v < 200000) { c = 2; l = 40000; }
        else                 { c = 3; l = 200000; }
        rank = atomicAdd(&s_cnt[c], 1);
    }
    __syncthreads();
    if (threadIdx.x < 4)
        s_base[threadIdx.x] = atomicAdd(&g_cnt[threadIdx.x], s_cnt[threadIdx.x]);
    __syncthreads();
    if (valid) {
        const int p = s_base[c] + rank;
        g_tok[c][p] = t;
        g_loc[c][p] = v - l;
    }
}

// ---------------- kernel: fused tf32 fragment-layout conversion + plan ----------------
// A layout: [mtile][k16][st(8)][k8r(2)][lane(32)][4]
// B layout: [ntile(128)][k16][lane(32)][4]
__global__ void conv_kernel(
    const float* __restrict__ e0, const float* __restrict__ e1,
    const float* __restrict__ e2, const float* __restrict__ e3,
    const float* __restrict__ p0, const float* __restrict__ p1,
    const float* __restrict__ p2, const float* __restrict__ p3)
{
    if (blockIdx.y == 0 && blockIdx.x == 0) {
        __shared__ int offs[5];
        if (threadIdx.x == 0) {
            offs[0] = 0;
            for (int c = 0; c < 4; c++) offs[c + 1] = offs[c] + ((g_cnt[c] + 127) >> 7);
            g_total_tiles = offs[4];
        }
        __syncthreads();
        const int total = offs[4];
        for (int i = threadIdx.x; i < total; i += blockDim.x) {
            int c = 0;
            while (i >= offs[c + 1]) c++;
            g_tile_c[i] = c;
            g_tile_m0[i] = (i - offs[c]) << 7;
        }
    }

    const int y = blockIdx.y;
    const unsigned stride = gridDim.x * blockDim.x;
    const unsigned t0 = blockIdx.x * blockDim.x + threadIdx.x;

    if (y < 4) {
        const int c = y;
        const float* proj = c == 0 ? p0 : c == 1 ? p1 : c == 2 ? p2 : p3;
        const int K = c_K[c];
        const int lkk = c_logK[c] - 4;
        const unsigned base = c_BOFF[c];
        const unsigned nu = (unsigned)(K >> 4) << 12;
        for (unsigned u = t0; u < nu; u += stride) {
            const int lane = u & 31;
            const int k16  = (u >> 5) & ((1u << lkk) - 1);
            const int nt   = u >> (5 + lkk);
            const int n    = nt * 8 + (lane >> 2);
            const int cb   = k16 * 16 + (lane & 3);
            const float* p = proj + (size_t)n * K + cb;
            uint4 v = make_uint4(f2tf(p[0]), f2tf(p[4]), f2tf(p[8]), f2tf(p[12]));
            *reinterpret_cast<uint4*>(g_b + base + ((size_t)u << 2)) = v;
        }
    } else {
        const int c = y - 4;
        const float* emb = c == 0 ? e0 : c == 1 ? e1 : c == 2 ? e2 : e3;
        const int K = c_K[c];
        const int lkk = c_logK[c] - 4;
        const int cnt = g_cnt[c];
        const unsigned base = c_AOFF[c];
        const int mtiles = (cnt + 127) >> 7;
        const unsigned nu = (unsigned)mtiles * ((unsigned)(K >> 4) << 9);
        for (unsigned u = t0; u < nu; u += stride) {
            const int lane  = u & 31;
            const int k8r   = (u >> 5) & 1;
            const int st    = (u >> 6) & 7;
            const int k16   = (u >> 9) & ((1u << lkk) - 1);
            const int mtile = u >> (9 + lkk);
            const int r0 = mtile * 128 + st * 16 + (lane >> 2);
            const int r1 = r0 + 8;
            const int cb = k16 * 16 + k8r * 8 + (lane & 3);
            float x0 = 0.f, x1 = 0.f, x2 = 0.f, x3 = 0.f;
            if (r0 < cnt) {
                const float* p = emb + (size_t)g_loc[c][r0] * K + cb;
                x0 = p[0]; x2 = p[4];
            }
            if (r1 < cnt) {
                const float* p = emb + (size_t)g_loc[c][r1] * K + cb;
                x1 = p[0]; x3 = p[4];
            }
            uint4 v = make_uint4(f2tf(x0), f2tf(x1), f2tf(x2), f2tf(x3));
            *reinterpret_cast<uint4*>(g_a + base + ((size_t)u << 2)) = v;
        }
    }
}

// ---------------- kernel: tf32 cp.async-pipelined GEMM ----------------
// BM=128, BN=64, BK=32. Stage: A 16KB + B 8KB = 24KB; NS=3 -> 72KB; 3 CTAs/SM.
#define STG_A 0
#define STG_B 16384
#define STG_STRIDE 24576
#define SMEM_BYTES (NS * STG_STRIDE)

__global__ __launch_bounds__(NTHREADS, 3) void gemm_mma_kernel(float* __restrict__ out) {
    extern __shared__ char smem[];
    const uint32_t sb = smem_u32(smem);

    const int tile = blockIdx.y;
    if (tile >= g_total_tiles) return;

    const int cluster = g_tile_c[tile];
    const int m0 = g_tile_m0[tile];
    const int cnt = g_cnt[cluster];
    const int K = c_K[cluster];
    const int lkk = c_logK[cluster] - 4;
    const int n0 = blockIdx.x * 64;

    const float* abase = g_a + c_AOFF[cluster] + (size_t)m0 * K;
    const float* bbase = g_b + c_BOFF[cluster];
    const int ntg0 = n0 >> 3;

    const int tid  = threadIdx.x;
    const int lane = tid & 31;
    const int wid  = tid >> 5;

    const int nchunks = (K + 31) >> 5;

    auto issue = [&](int ic) {
        const int k16a = ic << 1;
        const int nk16 = ((K >> 4) - k16a) >= 2 ? 2 : 1;
        const uint32_t bo = sb + (uint32_t)(ic % NS) * STG_STRIDE;
        // A: contiguous nk16*8KB
        const float* asrc = abase + ((size_t)k16a << 11);
        const int agr = nk16 << 9;
        for (int ci = tid; ci < agr; ci += NTHREADS)
            cp16(bo + STG_A + ci * 16, asrc + ci * 4);
        // B: 8 ntiles, each contiguous nk16*512B
        const int lgb = 5 + (nk16 >> 1);
        const int bgr = nk16 << 8;
        for (int ci = tid; ci < bgr; ci += NTHREADS) {
            const int nt = ci >> lgb;
            const int rem = ci & ((1 << lgb) - 1);
            const float* bsrc =
                bbase + ((((size_t)(ntg0 + nt) << lkk) + k16a) << 7) + rem * 4;
            cp16(bo + STG_B + (nt << (lgb + 4)) + (rem << 4), bsrc);
        }
    };

    for (int s = 0; s < NS - 1; s++) {
        if (s < nchunks) issue(s);
        CP_COMMIT();
    }

    float acc[2][4][4] = {};

    auto kstep = [&](uint32_t bo, int k16r, int bstr) {
        uint32_t aA[2][4], aB[2][4];
#pragma unroll
        for (int mt = 0; mt < 2; mt++) {
            const int st = (wid & 3) * 2 + mt;
            const uint32_t ad = bo + STG_A + k16r * 8192 + st * 1024 + lane * 16;
            lds128(aA[mt], ad);
            lds128(aB[mt], ad + 512);
        }
#pragma unroll
        for (int nt = 0; nt < 4; nt++) {
            const int ntb = (wid >> 2) * 4 + nt;
            uint32_t b[4];
            lds128(b, bo + STG_B + ntb * bstr + k16r * 512 + lane * 16);
#pragma unroll
            for (int mt = 0; mt < 2; mt++) {
                mma_tf32(acc[mt][nt], aA[mt], b[0], b[1]);
                mma_tf32(acc[mt][nt], aB[mt], b[2], b[3]);
            }
        }
    };

    for (int ic = 0; ic < nchunks; ic++) {
        CP_WAIT1();
        __syncthreads();
        if (ic + NS - 1 < nchunks) issue(ic + NS - 1);
        CP_COMMIT();

        const int nk16 = ((K >> 4) - (ic << 1)) >= 2 ? 2 : 1;
        const int bstr = nk16 << 9;
        const uint32_t bo = sb + (uint32_t)(ic % NS) * STG_STRIDE;
        kstep(bo, 0, bstr);
        if (nk16 == 2) kstep(bo, 1, bstr);
    }

    // epilogue: scale + scatter
#pragma unroll
    for (int mt = 0; mt < 2; mt++) {
        const int r0 = m0 + (wid & 3) * 32 + mt * 16 + (lane >> 2);
        const int r1 = r0 + 8;
        const int ncol = n0 + (wid >> 2) * 32 + (lane & 3) * 2;
        float* q0 = nullptr;
        float* q1 = nullptr;
        if (r0 < cnt) q0 = out + (size_t)g_tok[cluster][r0] * D_PROJ + ncol;
        if (r1 < cnt) q1 = out + (size_t)g_tok[cluster][r1] * D_PROJ + ncol;
#pragma unroll
        for (int nt = 0; nt < 4; nt++) {
            if (q0) *reinterpret_cast<float2*>(q0 + nt * 8) =
                make_float2(acc[mt][nt][0] * EMB_SCALE, acc[mt][nt][1] * EMB_SCALE);
            if (q1) *reinterpret_cast<float2*>(q1 + nt * 8) =
                make_float2(acc[mt][nt][2] * EMB_SCALE, acc[mt][nt][3] * EMB_SCALE);
        }
    }
}

// ---------------- launch ----------------
extern "C" void kernel_launch(void* const* d_in, const int* in_sizes, int n_in,
                              void* d_out, int out_size) {
    const int* inp = (const int*)d_in[0];
    const float* emb[4];
    const float* proj[4];

    if (n_in >= 9 && in_sizes[2] == 1024 * 1024) {
        for (int i = 0; i < 4; i++) {
            emb[i]  = (const float*)d_in[1 + 2 * i];
            proj[i] = (const float*)d_in[2 + 2 * i];
        }
    } else {
        for (int i = 0; i < 4; i++) {
            emb[i]  = (const float*)d_in[1 + i];
            proj[i] = (const float*)d_in[5 + i];
        }
    }

    float* out = (float*)d_out;
    const int n_tok = in_sizes[0];

    static void* cnt_addr = nullptr;
    if (!cnt_addr) {
        cudaGetSymbolAddress(&cnt_addr, g_cnt);
        cudaFuncSetAttribute(gemm_mma_kernel,
                             cudaFuncAttributeMaxDynamicSharedMemorySize, SMEM_BYTES);
    }

    // graph-capturable memset node replaces zero_kernel launch
    cudaMemsetAsync(cnt_addr, 0, 4 * sizeof(int));

    bucket_kernel<<<(n_tok + 255) / 256, 256>>>(inp, n_tok);
    conv_kernel<<<dim3(512, 8), 256>>>(emb[0], emb[1], emb[2], emb[3],
                                       proj[0], proj[1], proj[2], proj[3]);

    dim3 grid(D_PROJ / 64, MAX_TILES);
    gemm_mma_kernel<<<grid, NTHREADS, SMEM_BYTES>>>(out);
}